// round 5
// baseline (speedup 1.0000x reference)
#include <cuda_runtime.h>

#define WID 512
#define HEI 512
#define NPIX (WID*HEI)
#define RAD 10
#define KS 21
#define VR 8            // rows per thread in vertical passes
#define HW (WID + 2*RAD) // 532: full row + halo

// ---------------- compile-time weights (double-precision constexpr exp) ----------------
constexpr double cexp(double x) {
    double y = x / 16.0, s = 1.0, t = 1.0;
    for (int i = 1; i < 40; i++) { t *= y / (double)i; s += t; }
    s = s * s; s = s * s; s = s * s; s = s * s;
    return s;
}
constexpr double wgd(int t) { double d = (double)(t - RAD); return cexp(-d * d / 12.5); }          // theta=2.5
constexpr double wdd(int t) { double d = (double)(t - RAD); return cexp(-d * d * 9.0 / 200.0); }   // theta=10/3
constexpr double sumw(int wh) { double s = 0; for (int i = 0; i < KS; i++) s += (wh ? wgd(i) : wdd(i)); return s; }
constexpr double pref(int wh, int n) { double s = 0; for (int i = 0; i < n; i++) s += (wh ? wgd(i) : wdd(i)); return s; }

constexpr float SD_F    = (float)sumw(0);
constexpr float SG_F    = (float)sumw(1);
constexpr float SDINV_F = (float)(1.0 / (sumw(0) * sumw(0)));

#define TAPLIST(F) F(0) F(1) F(2) F(3) F(4) F(5) F(6) F(7) F(8) F(9) F(10) \
                   F(11) F(12) F(13) F(14) F(15) F(16) F(17) F(18) F(19) F(20)
#define DWG(i) constexpr float WG_##i = (float)wgd(i);
#define DWD(i) constexpr float WD_##i = (float)wdd(i);
TAPLIST(DWG)
TAPLIST(DWD)

// switch on literal -> constant-folds after unroll -> FFMA with immediate multiplier
__device__ __forceinline__ float wG(int t) {
    switch (t) {
#define CWG(i) case i: return WG_##i;
        TAPLIST(CWG)
#undef CWG
    }
    return 0.f;
}
__device__ __forceinline__ float wD(int t) {
    switch (t) {
#define CWD(i) case i: return WD_##i;
        TAPLIST(CWD)
#undef CWD
    }
    return 0.f;
}

// prefix sums for border-truncated 1D sums (runtime index, tiny -> __constant__)
__constant__ float c_pD[11] = {
    (float)pref(0,0),(float)pref(0,1),(float)pref(0,2),(float)pref(0,3),(float)pref(0,4),
    (float)pref(0,5),(float)pref(0,6),(float)pref(0,7),(float)pref(0,8),(float)pref(0,9),
    (float)pref(0,10)
};
__constant__ float c_pG[11] = {
    (float)pref(1,0),(float)pref(1,1),(float)pref(1,2),(float)pref(1,3),(float)pref(1,4),
    (float)pref(1,5),(float)pref(1,6),(float)pref(1,7),(float)pref(1,8),(float)pref(1,9),
    (float)pref(1,10)
};

__device__ __forceinline__ float hsD(int x) {
    float s = SD_F;
    if (x < RAD) s -= c_pD[RAD - x];
    if (x > WID - 1 - RAD) s -= c_pD[x - (WID - 1 - RAD)];
    return s;
}
__device__ __forceinline__ float hsG(int x) {
    float s = SG_F;
    if (x < RAD) s -= c_pG[RAD - x];
    if (x > WID - 1 - RAD) s -= c_pG[x - (WID - 1 - RAD)];
    return s;
}

// ---------------- static device scratch ----------------
__device__ float  g_gray[NPIX];
__device__ float  g_meanI[NPIX];
__device__ float  g_invvar[NPIX];
__device__ float  g_bnorm[NPIX];
__device__ float  g_s1[NPIX], g_s2[NPIX];
__device__ float  g_a1[NPIX], g_b1[NPIX];
__device__ float4 g_Q[NPIX];
__device__ float4 g_t1[NPIX], g_t2[NPIX], g_t3[NPIX];
__device__ float4 g_a[NPIX], g_b[NPIX], g_sp[NPIX];

// ---------------- helpers ----------------
__device__ __forceinline__ float4 zero4() { return make_float4(0.f, 0.f, 0.f, 0.f); }
__device__ __forceinline__ void fma4(float4& a, float w, const float4& v) {
    a.x = fmaf(w, v.x, a.x); a.y = fmaf(w, v.y, a.y);
    a.z = fmaf(w, v.z, a.z); a.w = fmaf(w, v.w, a.w);
}
__device__ __forceinline__ float4 softmax4(float4 z) {
    float m = fmaxf(fmaxf(z.x, z.y), fmaxf(z.z, z.w));
    float ex = __expf(z.x - m), ey = __expf(z.y - m);
    float ez = __expf(z.z - m), ew = __expf(z.w - m);
    float inv = 1.f / (ex + ey + ez + ew);
    return make_float4(ex * inv, ey * inv, ez * inv, ew * inv);
}

// ---------------- prep: grayscale + Q0 = softmax(-unary) ----------------
__global__ void k_prep(const float* __restrict__ img, const float4* __restrict__ unary) {
    int i = blockIdx.x * blockDim.x + threadIdx.x;
    if (i >= NPIX) return;
    g_gray[i] = 0.2989f * img[3 * i] + 0.5870f * img[3 * i + 1] + 0.1140f * img[3 * i + 2];
    float4 u = unary[i];
    g_Q[i] = softmax4(make_float4(-u.x, -u.y, -u.z, -u.w));
}

// ---------------- scalar horizontal (guided weights), RX=4, full row ----------------
// MODE 0: gray, gray^2 -> s1, s2 ; MODE 1: a1, b1 -> s1, s2
template <int MODE>
__global__ void __launch_bounds__(128) k_hscalar() {
    __shared__ float s1[HW], s2[HW];
    int y = blockIdx.x, tid = threadIdx.x;
    for (int s = tid; s < HW; s += 128) {
        int x = s - RAD;
        float a = 0.f, b = 0.f;
        if ((unsigned)x < WID) {
            int p = y * WID + x;
            if (MODE == 0) { a = g_gray[p]; b = a * a; }
            else           { a = g_a1[p];  b = g_b1[p]; }
        }
        s1[s] = a; s2[s] = b;
    }
    __syncthreads();
    int x0 = tid * 4;
    float A[4] = {0, 0, 0, 0}, B[4] = {0, 0, 0, 0};
#pragma unroll
    for (int j = 0; j < KS + 3; j++) {
        float v1 = s1[x0 + j], v2 = s2[x0 + j];
#pragma unroll
        for (int r = 0; r < 4; r++) {
            int t = j - r;
            if (t >= 0 && t < KS) {
                A[r] = fmaf(wD(t), v1, A[r]);
                B[r] = fmaf(wD(t), v2, B[r]);
            }
        }
    }
    int o = y * WID + x0;
#pragma unroll
    for (int r = 0; r < 4; r++) { g_s1[o + r] = A[r]; g_s2[o + r] = B[r]; }
}

// ---------------- scalar vertical 1: meanI / invvar / a1 / b1 ----------------
__global__ void __launch_bounds__(128) k_vpre1() {
    int x = blockIdx.x * 128 + threadIdx.x;
    int y0 = blockIdx.y * VR;
    float A1[VR], A2[VR];
#pragma unroll
    for (int r = 0; r < VR; r++) { A1[r] = 0.f; A2[r] = 0.f; }
#pragma unroll
    for (int j = 0; j < KS + VR - 1; j++) {
        int row = y0 + j - RAD;
        float v1 = 0.f, v2 = 0.f;
        if ((unsigned)row < HEI) { int p = row * WID + x; v1 = g_s1[p]; v2 = g_s2[p]; }
#pragma unroll
        for (int r = 0; r < VR; r++) {
            int t = j - r;
            if (t >= 0 && t < KS) {
                A1[r] = fmaf(wD(t), v1, A1[r]);
                A2[r] = fmaf(wD(t), v2, A2[r]);
            }
        }
    }
    float hdx = hsD(x);
#pragma unroll
    for (int r = 0; r < VR; r++) {
        int y = y0 + r, idx = y * WID + x;
        float g = g_gray[idx];
        float mI  = (A1[r] - g) * SDINV_F;
        float mII = (A2[r] - g * g) * SDINV_F;
        float mp1 = (hdx * hsD(y) - 1.f) * SDINV_F;
        float var = mII - mI * mI;
        float iv  = 1.f / (var + 1e-4f);
        float a1  = mI * (1.f - mp1) * iv;
        float b1  = mp1 - a1 * mI;
        g_meanI[idx] = mI; g_invvar[idx] = iv; g_a1[idx] = a1; g_b1[idx] = b1;
    }
}

// ---------------- scalar vertical 2: bilateral norm ----------------
__global__ void __launch_bounds__(128) k_vpre2() {
    int x = blockIdx.x * 128 + threadIdx.x;
    int y0 = blockIdx.y * VR;
    float A1[VR], A2[VR];
#pragma unroll
    for (int r = 0; r < VR; r++) { A1[r] = 0.f; A2[r] = 0.f; }
#pragma unroll
    for (int j = 0; j < KS + VR - 1; j++) {
        int row = y0 + j - RAD;
        float v1 = 0.f, v2 = 0.f;
        if ((unsigned)row < HEI) { int p = row * WID + x; v1 = g_s1[p]; v2 = g_s2[p]; }
#pragma unroll
        for (int r = 0; r < VR; r++) {
            int t = j - r;
            if (t >= 0 && t < KS) {
                A1[r] = fmaf(wD(t), v1, A1[r]);
                A2[r] = fmaf(wD(t), v2, A2[r]);
            }
        }
    }
#pragma unroll
    for (int r = 0; r < VR; r++) {
        int idx = (y0 + r) * WID + x;
        float g = g_gray[idx];
        float gfa = (A1[r] - g_a1[idx]) * SDINV_F;
        float gfb = (A2[r] - g_b1[idx]) * SDINV_F;
        g_bnorm[idx] = gfa * g + gfb;
    }
}

// ---------------- iteration: H pass of Q (3 float4 channels), RX=4, full row ----------------
__global__ void __launch_bounds__(128) k_hiter() {
    __shared__ float4 sQ[HW];
    __shared__ float  sG[HW];
    int y = blockIdx.x, tid = threadIdx.x;
    const float4* Qrow = g_Q + y * WID;
    const float*  Grow = g_gray + y * WID;
    for (int s = tid; s < HW; s += 128) {
        int x = s - RAD;
        float4 q = zero4(); float g = 0.f;
        if ((unsigned)x < WID) { q = Qrow[x]; g = Grow[x]; }
        sQ[s] = q; sG[s] = g;
    }
    __syncthreads();
    int x0 = tid * 4;
    float4 AG[4], AD[4], AI[4];
#pragma unroll
    for (int r = 0; r < 4; r++) { AG[r] = zero4(); AD[r] = zero4(); AI[r] = zero4(); }
#pragma unroll
    for (int j = 0; j < KS + 3; j++) {
        float4 q = sQ[x0 + j];
        float  g = sG[x0 + j];
        float4 gq = make_float4(q.x * g, q.y * g, q.z * g, q.w * g);
#pragma unroll
        for (int r = 0; r < 4; r++) {
            int t = j - r;
            if (t >= 0 && t < KS) {
                fma4(AG[r], wG(t), q);
                fma4(AD[r], wD(t), q);
                fma4(AI[r], wD(t), gq);
            }
        }
    }
    int o = y * WID + x0;
#pragma unroll
    for (int r = 0; r < 4; r++) { g_t1[o + r] = AG[r]; g_t2[o + r] = AD[r]; g_t3[o + r] = AI[r]; }
}

// ---------------- iteration: V pass + a/b/spatial elementwise ----------------
__global__ void __launch_bounds__(128) k_viter() {
    int x = blockIdx.x * 128 + threadIdx.x;
    int y0 = blockIdx.y * VR;
    float4 AG[VR], AD[VR], AI[VR];
#pragma unroll
    for (int r = 0; r < VR; r++) { AG[r] = zero4(); AD[r] = zero4(); AI[r] = zero4(); }
#pragma unroll
    for (int j = 0; j < KS + VR - 1; j++) {
        int row = y0 + j - RAD;
        float4 v1 = zero4(), v2 = zero4(), v3 = zero4();
        if ((unsigned)row < HEI) {
            int p = row * WID + x;
            v1 = g_t1[p]; v2 = g_t2[p]; v3 = g_t3[p];
        }
#pragma unroll
        for (int r = 0; r < VR; r++) {
            int t = j - r;
            if (t >= 0 && t < KS) {
                fma4(AG[r], wG(t), v1);
                fma4(AD[r], wD(t), v2);
                fma4(AI[r], wD(t), v3);
            }
        }
    }
    float hgx = hsG(x);
#pragma unroll
    for (int r = 0; r < VR; r++) {
        int y = y0 + r, idx = y * WID + x;
        float4 q = g_Q[idx];
        float g = g_gray[idx], mI = g_meanI[idx], iv = g_invvar[idx];
        float spc = 3.f / (hgx * hsG(y) - 1.f);    // S_G^2 cancels between conv and norm
        float4 sp = make_float4((AG[r].x - q.x) * spc, (AG[r].y - q.y) * spc,
                                (AG[r].z - q.z) * spc, (AG[r].w - q.w) * spc);
        float4 mp  = make_float4((AD[r].x - q.x) * SDINV_F, (AD[r].y - q.y) * SDINV_F,
                                 (AD[r].z - q.z) * SDINV_F, (AD[r].w - q.w) * SDINV_F);
        float4 mIp = make_float4((AI[r].x - g * q.x) * SDINV_F, (AI[r].y - g * q.y) * SDINV_F,
                                 (AI[r].z - g * q.z) * SDINV_F, (AI[r].w - g * q.w) * SDINV_F);
        float4 a = make_float4((mIp.x - mI * mp.x) * iv, (mIp.y - mI * mp.y) * iv,
                               (mIp.z - mI * mp.z) * iv, (mIp.w - mI * mp.w) * iv);
        float4 b = make_float4(mp.x - a.x * mI, mp.y - a.y * mI,
                               mp.z - a.z * mI, mp.w - a.w * mI);
        g_a[idx] = a; g_b[idx] = b; g_sp[idx] = sp;
    }
}

// ---------------- iteration: H pass of a, b ----------------
__global__ void __launch_bounds__(128) k_hab() {
    __shared__ float4 sA[HW], sB[HW];
    int y = blockIdx.x, tid = threadIdx.x;
    const float4* Arow = g_a + y * WID;
    const float4* Brow = g_b + y * WID;
    for (int s = tid; s < HW; s += 128) {
        int x = s - RAD;
        float4 a = zero4(), b = zero4();
        if ((unsigned)x < WID) { a = Arow[x]; b = Brow[x]; }
        sA[s] = a; sB[s] = b;
    }
    __syncthreads();
    int x0 = tid * 4;
    float4 AA[4], AB[4];
#pragma unroll
    for (int r = 0; r < 4; r++) { AA[r] = zero4(); AB[r] = zero4(); }
#pragma unroll
    for (int j = 0; j < KS + 3; j++) {
        float4 va = sA[x0 + j], vb = sB[x0 + j];
#pragma unroll
        for (int r = 0; r < 4; r++) {
            int t = j - r;
            if (t >= 0 && t < KS) {
                fma4(AA[r], wD(t), va);
                fma4(AB[r], wD(t), vb);
            }
        }
    }
    int o = y * WID + x0;
#pragma unroll
    for (int r = 0; r < 4; r++) { g_t1[o + r] = AA[r]; g_t2[o + r] = AB[r]; }
}

// ---------------- iteration: V pass of a,b + message + softmax ----------------
template <bool FINAL>
__global__ void __launch_bounds__(128) k_vfin(const float4* __restrict__ unary,
                                              float4* __restrict__ dout) {
    int x = blockIdx.x * 128 + threadIdx.x;
    int y0 = blockIdx.y * VR;
    float4 AA[VR], AB[VR];
#pragma unroll
    for (int r = 0; r < VR; r++) { AA[r] = zero4(); AB[r] = zero4(); }
#pragma unroll
    for (int j = 0; j < KS + VR - 1; j++) {
        int row = y0 + j - RAD;
        float4 v1 = zero4(), v2 = zero4();
        if ((unsigned)row < HEI) { int p = row * WID + x; v1 = g_t1[p]; v2 = g_t2[p]; }
#pragma unroll
        for (int r = 0; r < VR; r++) {
            int t = j - r;
            if (t >= 0 && t < KS) {
                fma4(AA[r], wD(t), v1);
                fma4(AB[r], wD(t), v2);
            }
        }
    }
#pragma unroll
    for (int r = 0; r < VR; r++) {
        int idx = (y0 + r) * WID + x;
        float g = g_gray[idx];
        float ibn = 10.f / g_bnorm[idx];    // bilateral compat weight folded in
        float4 av = g_a[idx], bv = g_b[idx], sp = g_sp[idx], u = unary[idx];
        float4 z;
        z.x = sp.x + ((AA[r].x - av.x) * SDINV_F * g + (AB[r].x - bv.x) * SDINV_F) * ibn - u.x;
        z.y = sp.y + ((AA[r].y - av.y) * SDINV_F * g + (AB[r].y - bv.y) * SDINV_F) * ibn - u.y;
        z.z = sp.z + ((AA[r].z - av.z) * SDINV_F * g + (AB[r].z - bv.z) * SDINV_F) * ibn - u.z;
        z.w = sp.w + ((AA[r].w - av.w) * SDINV_F * g + (AB[r].w - bv.w) * SDINV_F) * ibn - u.w;
        float4 qn = softmax4(z);
        if (FINAL) dout[idx] = qn; else g_Q[idx] = qn;
    }
}

// ---------------- launch ----------------
extern "C" void kernel_launch(void* const* d_in, const int* in_sizes, int n_in,
                              void* d_out, int out_size) {
    const float* unary = nullptr;
    const float* image = nullptr;
    for (int i = 0; i < n_in; i++) {
        if (in_sizes[i] == NPIX * 4) unary = (const float*)d_in[i];
        else if (in_sizes[i] == NPIX * 3) image = (const float*)d_in[i];
    }

    dim3 bh(128), gh(HEI);                  // one full row per block, RX=4
    dim3 bv(128), gv(WID / 128, HEI / VR);  // vertical: 4 x 64 blocks

    k_prep<<<NPIX / 256, 256>>>(image, (const float4*)unary);

    // image-only precompute (mean_I, inv_var, bilateral norm)
    k_hscalar<0><<<gh, bh>>>();
    k_vpre1<<<gv, bv>>>();
    k_hscalar<1><<<gh, bh>>>();
    k_vpre2<<<gv, bv>>>();

    // 5 mean-field iterations
    for (int it = 0; it < 5; it++) {
        k_hiter<<<gh, bh>>>();
        k_viter<<<gv, bv>>>();
        k_hab<<<gh, bh>>>();
        if (it < 4) k_vfin<false><<<gv, bv>>>((const float4*)unary, nullptr);
        else        k_vfin<true><<<gv, bv>>>((const float4*)unary, (float4*)d_out);
    }
}